// round 1
// baseline (speedup 1.0000x reference)
#include <cuda_runtime.h>
#include <cstdint>

#define THREADS 256
#define BTILE   32
#define NB      8       // batches per thread
#define HD      64      // hidden
#define GD      256     // 4*H
#define TT      168
#define ID      4
#define WPAD    66      // padded row stride (floats), even for 8B-aligned f32x2 loads
#define HPAD    66
#define NGRID   128     // 4096 / 32

typedef unsigned long long u64;

__device__ __forceinline__ u64 ld64s(const float* p) {
    return *reinterpret_cast<const u64*>(p);
}
__device__ __forceinline__ void ffma2(u64 &d, u64 a, u64 b) {
    asm("fma.rn.f32x2 %0, %1, %2, %0;" : "+l"(d) : "l"(a), "l"(b));
}
__device__ __forceinline__ float red2(u64 v) {
    return __uint_as_float((unsigned)v) + __uint_as_float((unsigned)(v >> 32));
}
__device__ __forceinline__ u64 pack2(float lo, float hi) {
    return (u64)__float_as_uint(lo) | ((u64)__float_as_uint(hi) << 32);
}
__device__ __forceinline__ float fsig(float x) {
    return __fdividef(1.0f, 1.0f + __expf(-x));
}
__device__ __forceinline__ float ftanh(float x) {
    return __fdividef(2.0f, 1.0f + __expf(-2.0f * x)) - 1.0f;
}

extern "C" __global__ void __launch_bounds__(THREADS, 1)
weather_lstm_kernel(const float* __restrict__ x,
                    const float* __restrict__ Wih0, const float* __restrict__ Whh0,
                    const float* __restrict__ bih0, const float* __restrict__ bhh0,
                    const float* __restrict__ Wih1, const float* __restrict__ Whh1,
                    const float* __restrict__ bih1, const float* __restrict__ bhh1,
                    const float* __restrict__ W1,  const float* __restrict__ b1,
                    const float* __restrict__ W2,  const float* __restrict__ b2,
                    float* __restrict__ out)
{
    extern __shared__ float sm[];
    float* sW0  = sm;                       // Whh0 [256][66]
    float* sW1i = sW0  + GD * WPAD;         // Wih1 [256][66]
    float* sW1h = sW1i + GD * WPAD;         // Whh1 [256][66]
    float* sH0  = sW1h + GD * WPAD;         // h of layer0 [32][66]
    float* sH1  = sH0  + BTILE * HPAD;      // h of layer1 [32][66]
    float* sX   = sH1  + BTILE * HPAD;      // x_t [32][4]

    const int t     = threadIdx.x;
    const int u     = t & 63;               // hidden unit owned by this thread
    const int b0    = (t >> 6) * NB;        // first local batch
    const int bBase = blockIdx.x * BTILE;

    // ---- preload weights into SMEM (coalesced LDG, conflict-free STS) ----
    for (int e = t; e < GD * HD; e += THREADS) {
        int j = e >> 6, k = e & 63;
        sW0 [j * WPAD + k] = Whh0[e];
        sW1i[j * WPAD + k] = Wih1[e];
        sW1h[j * WPAD + k] = Whh1[e];
    }
    for (int e = t; e < BTILE * HPAD; e += THREADS) { sH0[e] = 0.f; sH1[e] = 0.f; }
    if (t < BTILE * ID) {
        int b = t >> 2, i = t & 3;
        sX[b * ID + i] = x[(size_t)(bBase + b) * (TT * ID) + i];
    }

    // ---- per-thread constants ----
    float bias0[4], bias1[4], w0x[4][4];
    #pragma unroll
    for (int g = 0; g < 4; g++) {
        int j = u + 64 * g;
        bias0[g] = bih0[j] + bhh0[j];
        bias1[g] = bih1[j] + bhh1[j];
        #pragma unroll
        for (int i = 0; i < ID; i++) w0x[g][i] = Wih0[j * ID + i];
    }
    float c0[NB], c1[NB];
    #pragma unroll
    for (int b = 0; b < NB; b++) { c0[b] = 0.f; c1[b] = 0.f; }

    __syncthreads();

    for (int step = 0; step < TT; step++) {
        // prefetch x for step+1 (latency hidden behind layer-0 matvec)
        float xpre = 0.f;
        const int bpre = t >> 2, ipre = t & 3;
        if (t < BTILE * ID && step + 1 < TT)
            xpre = x[(size_t)(bBase + bpre) * (TT * ID) + (step + 1) * ID + ipre];

        // ================= layer 0 =================
        u64 acc0[4][NB];
        #pragma unroll
        for (int b = 0; b < NB; b++) {
            float4 xb = *reinterpret_cast<const float4*>(&sX[(b0 + b) * ID]);
            #pragma unroll
            for (int g = 0; g < 4; g++) {
                float a = bias0[g] + w0x[g][0] * xb.x + w0x[g][1] * xb.y
                                   + w0x[g][2] * xb.z + w0x[g][3] * xb.w;
                acc0[g][b] = pack2(a, 0.f);
            }
        }
        #pragma unroll 4
        for (int k = 0; k < HD; k += 2) {
            u64 w[4], h[NB];
            #pragma unroll
            for (int g = 0; g < 4; g++) w[g] = ld64s(&sW0[(u + 64 * g) * WPAD + k]);
            #pragma unroll
            for (int b = 0; b < NB; b++) h[b] = ld64s(&sH0[(b0 + b) * HPAD + k]);
            #pragma unroll
            for (int g = 0; g < 4; g++)
                #pragma unroll
                for (int b = 0; b < NB; b++) ffma2(acc0[g][b], w[g], h[b]);
        }
        float hnew0[NB];
        #pragma unroll
        for (int b = 0; b < NB; b++) {
            float gi = fsig (red2(acc0[0][b]));
            float gf = fsig (red2(acc0[1][b]));
            float gg = ftanh(red2(acc0[2][b]));
            float go = fsig (red2(acc0[3][b]));
            c0[b] = gf * c0[b] + gi * gg;
            hnew0[b] = go * ftanh(c0[b]);
        }
        __syncthreads();   // all reads of sH0 (h0_{t-1}) and sX done
        #pragma unroll
        for (int b = 0; b < NB; b++) sH0[(b0 + b) * HPAD + u] = hnew0[b];
        if (t < BTILE * ID) sX[bpre * ID + ipre] = xpre;
        __syncthreads();   // new h0_t visible

        // ================= layer 1 =================
        u64 acc1[4][NB];
        #pragma unroll
        for (int g = 0; g < 4; g++)
            #pragma unroll
            for (int b = 0; b < NB; b++) acc1[g][b] = pack2(bias1[g], 0.f);
        #pragma unroll 2
        for (int k = 0; k < HD; k += 2) {
            u64 wi[4], wh[4], hp0[NB], hp1[NB];
            #pragma unroll
            for (int g = 0; g < 4; g++) {
                wi[g] = ld64s(&sW1i[(u + 64 * g) * WPAD + k]);
                wh[g] = ld64s(&sW1h[(u + 64 * g) * WPAD + k]);
            }
            #pragma unroll
            for (int b = 0; b < NB; b++) {
                hp0[b] = ld64s(&sH0[(b0 + b) * HPAD + k]);
                hp1[b] = ld64s(&sH1[(b0 + b) * HPAD + k]);
            }
            #pragma unroll
            for (int g = 0; g < 4; g++)
                #pragma unroll
                for (int b = 0; b < NB; b++) {
                    ffma2(acc1[g][b], wi[g], hp0[b]);
                    ffma2(acc1[g][b], wh[g], hp1[b]);
                }
        }
        float hnew1[NB];
        #pragma unroll
        for (int b = 0; b < NB; b++) {
            float gi = fsig (red2(acc1[0][b]));
            float gf = fsig (red2(acc1[1][b]));
            float gg = ftanh(red2(acc1[2][b]));
            float go = fsig (red2(acc1[3][b]));
            c1[b] = gf * c1[b] + gi * gg;
            hnew1[b] = go * ftanh(c1[b]);
        }
        __syncthreads();   // all reads of sH1 (h1_{t-1}) done
        #pragma unroll
        for (int b = 0; b < NB; b++) sH1[(b0 + b) * HPAD + u] = hnew1[b];
        // no 4th barrier needed: next readers of sH1 are after next step's 2nd barrier
    }

    __syncthreads();       // final sH1 visible to everyone

    // ================= MLP head =================
    // reuse sW0 region for W1 transposed: W1s[k*64 + n] = W1[n*64 + k]
    float* W1s = sW0;
    for (int e = t; e < HD * HD; e += THREADS) {
        int n = e >> 6, k = e & 63;
        W1s[k * 64 + n] = W1[e];
    }
    __syncthreads();

    // z[b][n] = relu(b1[n] + sum_k W1[n][k] * h1[b][k]); thread owns n=u, 8 batches
    float bb1 = b1[u];
    float zv[NB];
    #pragma unroll
    for (int b = 0; b < NB; b++) {
        float s = bb1;
        #pragma unroll 8
        for (int k = 0; k < HD; k++)
            s += W1s[k * 64 + u] * sH1[(b0 + b) * HPAD + k];
        zv[b] = fmaxf(s, 0.f);
    }
    __syncthreads();       // done reading sH0-region? (sH0 untouched) — guards W1s reads done before sZ reuse? sZ uses sH0, safe; this barrier orders zv stores below
    float* sZ = sH0;       // reuse: [b][66]
    #pragma unroll
    for (int b = 0; b < NB; b++) sZ[(b0 + b) * HPAD + u] = zv[b];
    __syncthreads();

    // out[b][o] = b2[o] + sum_n W2[o][n] * z[b][n]
    for (int e = t; e < BTILE * 12; e += THREADS) {
        int b = e / 12, o = e % 12;
        float s = __ldg(&b2[o]);
        #pragma unroll 8
        for (int n = 0; n < HD; n++)
            s += __ldg(&W2[o * 64 + n]) * sZ[b * HPAD + n];
        out[(size_t)(bBase + b) * 12 + o] = s;
    }
}

extern "C" void kernel_launch(void* const* d_in, const int* in_sizes, int n_in,
                              void* d_out, int out_size)
{
    (void)in_sizes; (void)n_in; (void)out_size;
    const size_t smem = (size_t)(3 * GD * WPAD + 2 * BTILE * HPAD + BTILE * ID) * sizeof(float);
    cudaFuncSetAttribute(weather_lstm_kernel,
                         cudaFuncAttributeMaxDynamicSharedMemorySize, (int)smem);
    weather_lstm_kernel<<<NGRID, THREADS, smem>>>(
        (const float*)d_in[0],
        (const float*)d_in[1],  (const float*)d_in[2],
        (const float*)d_in[3],  (const float*)d_in[4],
        (const float*)d_in[5],  (const float*)d_in[6],
        (const float*)d_in[7],  (const float*)d_in[8],
        (const float*)d_in[9],  (const float*)d_in[10],
        (const float*)d_in[11], (const float*)d_in[12],
        (float*)d_out);
}

// round 2
// speedup vs baseline: 1.1128x; 1.1128x over previous
#include <cuda_runtime.h>

#define THREADS 256
#define BTILE   32
#define NB      8       // batches per thread
#define HD      64      // hidden
#define GD      256     // 4*H
#define TT      168
#define ID      4
#define WP      68      // padded row stride: stride%32==4 words -> conflict-free LDS.128
#define NGRID   128     // 4096 / 32

typedef unsigned long long u64;

__device__ __forceinline__ void ffma2(u64 &d, u64 a, u64 b) {
    asm("fma.rn.f32x2 %0, %1, %2, %0;" : "+l"(d) : "l"(a), "l"(b));
}
__device__ __forceinline__ float red2(u64 v) {
    return __uint_as_float((unsigned)v) + __uint_as_float((unsigned)(v >> 32));
}
__device__ __forceinline__ u64 pack2(float lo, float hi) {
    return (u64)__float_as_uint(lo) | ((u64)__float_as_uint(hi) << 32);
}
__device__ __forceinline__ float tanhapx(float x) {
    float y; asm("tanh.approx.f32 %0, %1;" : "=f"(y) : "f"(x)); return y;
}
__device__ __forceinline__ float fsig(float x) {       // 1 MUFU + 2 FMA
    return fmaf(0.5f, tanhapx(0.5f * x), 0.5f);
}

extern "C" __global__ void __launch_bounds__(THREADS, 1)
weather_lstm_kernel(const float* __restrict__ x,
                    const float* __restrict__ Wih0, const float* __restrict__ Whh0,
                    const float* __restrict__ bih0, const float* __restrict__ bhh0,
                    const float* __restrict__ Wih1, const float* __restrict__ Whh1,
                    const float* __restrict__ bih1, const float* __restrict__ bhh1,
                    const float* __restrict__ W1,  const float* __restrict__ b1,
                    const float* __restrict__ W2,  const float* __restrict__ b2,
                    float* __restrict__ out)
{
    extern __shared__ float sm[];
    float* sW0  = sm;                       // Whh0 [256][68]
    float* sW1i = sW0  + GD * WP;           // Wih1 [256][68]
    float* sW1h = sW1i + GD * WP;           // Whh1 [256][68]
    float* sH0  = sW1h + GD * WP;           // h layer0 [32][68]
    float* sH1  = sH0  + BTILE * WP;        // h layer1 [32][68]
    float* sX   = sH1  + BTILE * WP;        // x_t [32][4]

    const int t     = threadIdx.x;
    const int u     = t & 63;               // hidden unit owned by this thread
    const int b0    = (t >> 6) * NB;        // first local batch
    const int bBase = blockIdx.x * BTILE;

    // ---- preload weights into SMEM ----
    for (int e = t; e < GD * HD; e += THREADS) {
        int j = e >> 6, k = e & 63;
        sW0 [j * WP + k] = Whh0[e];
        sW1i[j * WP + k] = Wih1[e];
        sW1h[j * WP + k] = Whh1[e];
    }
    for (int e = t; e < BTILE * WP; e += THREADS) { sH0[e] = 0.f; sH1[e] = 0.f; }
    if (t < BTILE * ID) {
        int b = t >> 2, i = t & 3;
        sX[b * ID + i] = x[(size_t)(bBase + b) * (TT * ID) + i];
    }

    // ---- per-thread constants ----
    float bias0[4], bias1[4], w0x[4][4];
    #pragma unroll
    for (int g = 0; g < 4; g++) {
        int j = u + 64 * g;
        bias0[g] = bih0[j] + bhh0[j];
        bias1[g] = bih1[j] + bhh1[j];
        #pragma unroll
        for (int i = 0; i < ID; i++) w0x[g][i] = Wih0[j * ID + i];
    }
    float c0[NB], c1[NB];
    #pragma unroll
    for (int b = 0; b < NB; b++) { c0[b] = 0.f; c1[b] = 0.f; }

    __syncthreads();

    for (int step = 0; step < TT; step++) {
        // prefetch x for step+1 (hidden behind layer-0 matvec)
        float xpre = 0.f;
        const int bpre = t >> 2, ipre = t & 3;
        if (t < BTILE * ID && step + 1 < TT)
            xpre = x[(size_t)(bBase + bpre) * (TT * ID) + (step + 1) * ID + ipre];

        // ================= layer 0 : acc = bias + Wih0*x + Whh0*h0 =========
        u64 acc0[4][NB];
        #pragma unroll
        for (int b = 0; b < NB; b++) {
            float4 xb = *reinterpret_cast<const float4*>(&sX[(b0 + b) * ID]);
            #pragma unroll
            for (int g = 0; g < 4; g++) {
                float a = bias0[g] + w0x[g][0] * xb.x + w0x[g][1] * xb.y
                                   + w0x[g][2] * xb.z + w0x[g][3] * xb.w;
                acc0[g][b] = pack2(a, 0.f);
            }
        }
        #pragma unroll 4
        for (int k = 0; k < HD; k += 4) {
            ulonglong2 w[4], h[NB];
            #pragma unroll
            for (int g = 0; g < 4; g++)
                w[g] = *reinterpret_cast<const ulonglong2*>(&sW0[(u + 64 * g) * WP + k]);
            #pragma unroll
            for (int b = 0; b < NB; b++)
                h[b] = *reinterpret_cast<const ulonglong2*>(&sH0[(b0 + b) * WP + k]);
            #pragma unroll
            for (int g = 0; g < 4; g++)
                #pragma unroll
                for (int b = 0; b < NB; b++) {
                    ffma2(acc0[g][b], w[g].x, h[b].x);
                    ffma2(acc0[g][b], w[g].y, h[b].y);
                }
        }
        float hnew0[NB];
        #pragma unroll
        for (int b = 0; b < NB; b++) {
            float gi = fsig   (red2(acc0[0][b]));
            float gf = fsig   (red2(acc0[1][b]));
            float gg = tanhapx(red2(acc0[2][b]));
            float go = fsig   (red2(acc0[3][b]));
            c0[b] = gf * c0[b] + gi * gg;
            hnew0[b] = go * tanhapx(c0[b]);
        }
        __syncthreads();   // all reads of sH0 (h0_{t-1}) and sX done
        #pragma unroll
        for (int b = 0; b < NB; b++) sH0[(b0 + b) * WP + u] = hnew0[b];
        if (t < BTILE * ID) sX[bpre * ID + ipre] = xpre;
        __syncthreads();   // new h0_t visible

        // ================= layer 1 : two k-passes to cap live registers ====
        u64 acc1[4][NB];
        #pragma unroll
        for (int g = 0; g < 4; g++)
            #pragma unroll
            for (int b = 0; b < NB; b++) acc1[g][b] = pack2(bias1[g], 0.f);

        #pragma unroll 4
        for (int k = 0; k < HD; k += 4) {        // pass A: Wih1 * h0_t
            ulonglong2 w[4], h[NB];
            #pragma unroll
            for (int g = 0; g < 4; g++)
                w[g] = *reinterpret_cast<const ulonglong2*>(&sW1i[(u + 64 * g) * WP + k]);
            #pragma unroll
            for (int b = 0; b < NB; b++)
                h[b] = *reinterpret_cast<const ulonglong2*>(&sH0[(b0 + b) * WP + k]);
            #pragma unroll
            for (int g = 0; g < 4; g++)
                #pragma unroll
                for (int b = 0; b < NB; b++) {
                    ffma2(acc1[g][b], w[g].x, h[b].x);
                    ffma2(acc1[g][b], w[g].y, h[b].y);
                }
        }
        #pragma unroll 4
        for (int k = 0; k < HD; k += 4) {        // pass B: Whh1 * h1_{t-1}
            ulonglong2 w[4], h[NB];
            #pragma unroll
            for (int g = 0; g < 4; g++)
                w[g] = *reinterpret_cast<const ulonglong2*>(&sW1h[(u + 64 * g) * WP + k]);
            #pragma unroll
            for (int b = 0; b < NB; b++)
                h[b] = *reinterpret_cast<const ulonglong2*>(&sH1[(b0 + b) * WP + k]);
            #pragma unroll
            for (int g = 0; g < 4; g++)
                #pragma unroll
                for (int b = 0; b < NB; b++) {
                    ffma2(acc1[g][b], w[g].x, h[b].x);
                    ffma2(acc1[g][b], w[g].y, h[b].y);
                }
        }
        float hnew1[NB];
        #pragma unroll
        for (int b = 0; b < NB; b++) {
            float gi = fsig   (red2(acc1[0][b]));
            float gf = fsig   (red2(acc1[1][b]));
            float gg = tanhapx(red2(acc1[2][b]));
            float go = fsig   (red2(acc1[3][b]));
            c1[b] = gf * c1[b] + gi * gg;
            hnew1[b] = go * tanhapx(c1[b]);
        }
        __syncthreads();   // all reads of sH1 (h1_{t-1}) done
        #pragma unroll
        for (int b = 0; b < NB; b++) sH1[(b0 + b) * WP + u] = hnew1[b];
        // next read of sH1 is after next step's 2nd barrier — no 4th barrier
    }

    __syncthreads();       // final sH1 visible

    // ================= MLP head =================
    float* W1s = sW0;      // reuse: W1 transposed [k][n]
    for (int e = t; e < HD * HD; e += THREADS) {
        int n = e >> 6, k = e & 63;
        W1s[k * 64 + n] = W1[e];
    }
    __syncthreads();

    float bb1 = b1[u];
    float zv[NB];
    #pragma unroll
    for (int b = 0; b < NB; b++) {
        float s = bb1;
        #pragma unroll 8
        for (int k = 0; k < HD; k++)
            s += W1s[k * 64 + u] * sH1[(b0 + b) * WP + k];
        zv[b] = fmaxf(s, 0.f);
    }
    __syncthreads();
    float* sZ = sH0;       // reuse
    #pragma unroll
    for (int b = 0; b < NB; b++) sZ[(b0 + b) * WP + u] = zv[b];
    __syncthreads();

    for (int e = t; e < BTILE * 12; e += THREADS) {
        int b = e / 12, o = e % 12;
        float s = __ldg(&b2[o]);
        #pragma unroll 8
        for (int n = 0; n < HD; n++)
            s += __ldg(&W2[o * 64 + n]) * sZ[b * WP + n];
        out[(size_t)(bBase + b) * 12 + o] = s;
    }
}

extern "C" void kernel_launch(void* const* d_in, const int* in_sizes, int n_in,
                              void* d_out, int out_size)
{
    (void)in_sizes; (void)n_in; (void)out_size;
    const size_t smem = (size_t)(3 * GD * WP + 2 * BTILE * WP + BTILE * ID) * sizeof(float);
    cudaFuncSetAttribute(weather_lstm_kernel,
                         cudaFuncAttributeMaxDynamicSharedMemorySize, (int)smem);
    weather_lstm_kernel<<<NGRID, THREADS, smem>>>(
        (const float*)d_in[0],
        (const float*)d_in[1],  (const float*)d_in[2],
        (const float*)d_in[3],  (const float*)d_in[4],
        (const float*)d_in[5],  (const float*)d_in[6],
        (const float*)d_in[7],  (const float*)d_in[8],
        (const float*)d_in[9],  (const float*)d_in[10],
        (const float*)d_in[11], (const float*)d_in[12],
        (float*)d_out);
}

// round 3
// speedup vs baseline: 1.1728x; 1.0539x over previous
#include <cuda_runtime.h>

#define THREADS 256
#define BTILE   32
#define NB      8       // batches per thread (and per warp-pair)
#define HD      64      // hidden
#define GD      256     // 4*H
#define TT      168
#define ID      4
#define WP      68      // padded row stride: stride%32==4 -> conflict-free LDS.128 (quarter-warp phases)
#define NGRID   128     // 4096 / 32

typedef unsigned long long u64;

__device__ __forceinline__ void ffma2(u64 &d, u64 a, u64 b) {
    asm("fma.rn.f32x2 %0, %1, %2, %0;" : "+l"(d) : "l"(a), "l"(b));
}
__device__ __forceinline__ float red2(u64 v) {
    return __uint_as_float((unsigned)v) + __uint_as_float((unsigned)(v >> 32));
}
__device__ __forceinline__ u64 pack2(float lo, float hi) {
    return (u64)__float_as_uint(lo) | ((u64)__float_as_uint(hi) << 32);
}
__device__ __forceinline__ float tanhapx(float x) {
    float y; asm("tanh.approx.f32 %0, %1;" : "=f"(y) : "f"(x)); return y;
}
__device__ __forceinline__ float fsig(float x) {       // 1 MUFU + 2 fma-ops
    return fmaf(0.5f, tanhapx(0.5f * x), 0.5f);
}
// 64-thread named barrier: warp-pair scoped sync (ids 1..4)
__device__ __forceinline__ void pairbar(int id) {
    asm volatile("bar.sync %0, 64;" :: "r"(id) : "memory");
}

extern "C" __global__ void __launch_bounds__(THREADS, 1)
weather_lstm_kernel(const float* __restrict__ x,
                    const float* __restrict__ Wih0, const float* __restrict__ Whh0,
                    const float* __restrict__ bih0, const float* __restrict__ bhh0,
                    const float* __restrict__ Wih1, const float* __restrict__ Whh1,
                    const float* __restrict__ bih1, const float* __restrict__ bhh1,
                    const float* __restrict__ W1,  const float* __restrict__ b1,
                    const float* __restrict__ W2,  const float* __restrict__ b2,
                    float* __restrict__ out)
{
    extern __shared__ float sm[];
    float* sW0  = sm;                       // Whh0 [256][68]
    float* sW1i = sW0  + GD * WP;           // Wih1 [256][68]
    float* sW1h = sW1i + GD * WP;           // Whh1 [256][68]
    float* sH0  = sW1h + GD * WP;           // h layer0 [32][68]   (pair-private rows)
    float* sH1  = sH0  + BTILE * WP;        // h layer1 [32][68]   (pair-private rows)
    float* sX   = sH1  + BTILE * WP;        // x_t [32][4]         (pair-private rows)

    const int t     = threadIdx.x;
    const int u     = t & 63;               // hidden unit owned by this thread
    const int pid   = t >> 6;               // warp-pair id (0..3)
    const int b0    = pid * NB;             // first batch of this pair
    const int barid = pid + 1;              // named barrier id
    const int bBase = blockIdx.x * BTILE;

    // ---- preload weights into SMEM ----
    for (int e = t; e < GD * HD; e += THREADS) {
        int j = e >> 6, k = e & 63;
        sW0 [j * WP + k] = Whh0[e];
        sW1i[j * WP + k] = Wih1[e];
        sW1h[j * WP + k] = Whh1[e];
    }
    for (int e = t; e < BTILE * WP; e += THREADS) { sH0[e] = 0.f; sH1[e] = 0.f; }
    // pair-private x load: first 32 threads of each pair load its 8 batches x 4 inputs
    const int lx   = u;                      // 0..63 within pair
    const int bpre = b0 + (lx >> 2);
    const int ipre = lx & 3;
    if (lx < 32)
        sX[bpre * ID + ipre] = x[(size_t)(bBase + bpre) * (TT * ID) + ipre];

    // ---- per-thread constants ----
    float bias0[4], bias1[4], w0x[4][4];
    #pragma unroll
    for (int g = 0; g < 4; g++) {
        int j = u + 64 * g;
        bias0[g] = bih0[j] + bhh0[j];
        bias1[g] = bih1[j] + bhh1[j];
        #pragma unroll
        for (int i = 0; i < ID; i++) w0x[g][i] = Wih0[j * ID + i];
    }
    float c0[NB], c1[NB];
    #pragma unroll
    for (int b = 0; b < NB; b++) { c0[b] = 0.f; c1[b] = 0.f; }

    __syncthreads();     // weights + initial state visible to all

    for (int step = 0; step < TT; step++) {
        // prefetch x for step+1 (hidden behind phase-1 matvecs)
        float xpre = 0.f;
        if (lx < 32 && step + 1 < TT)
            xpre = x[(size_t)(bBase + bpre) * (TT * ID) + (step + 1) * ID + ipre];

        // ======== phase 1a : layer0  acc0 = bias + Wih0*x + Whh0*h0_{t-1} ====
        u64 acc0[4][NB];
        #pragma unroll
        for (int b = 0; b < NB; b++) {
            float4 xb = *reinterpret_cast<const float4*>(&sX[(b0 + b) * ID]);
            #pragma unroll
            for (int g = 0; g < 4; g++) {
                float a = bias0[g] + w0x[g][0] * xb.x + w0x[g][1] * xb.y
                                   + w0x[g][2] * xb.z + w0x[g][3] * xb.w;
                acc0[g][b] = pack2(a, 0.f);
            }
        }
        #pragma unroll 4
        for (int k = 0; k < HD; k += 4) {
            ulonglong2 w[4], h[NB];
            #pragma unroll
            for (int g = 0; g < 4; g++)
                w[g] = *reinterpret_cast<const ulonglong2*>(&sW0[(u + 64 * g) * WP + k]);
            #pragma unroll
            for (int b = 0; b < NB; b++)
                h[b] = *reinterpret_cast<const ulonglong2*>(&sH0[(b0 + b) * WP + k]);
            #pragma unroll
            for (int g = 0; g < 4; g++)
                #pragma unroll
                for (int b = 0; b < NB; b++) {
                    ffma2(acc0[g][b], w[g].x, h[b].x);
                    ffma2(acc0[g][b], w[g].y, h[b].y);
                }
        }

        // ======== phase 1b : layer0 activations (MUFU) — overlaps with 1c ====
        float hnew0[NB];
        #pragma unroll
        for (int b = 0; b < NB; b++) {
            float gi = fsig   (red2(acc0[0][b]));
            float gf = fsig   (red2(acc0[1][b]));
            float gg = tanhapx(red2(acc0[2][b]));
            float go = fsig   (red2(acc0[3][b]));
            c0[b] = gf * c0[b] + gi * gg;
            hnew0[b] = go * tanhapx(c0[b]);
        }

        // ======== phase 1c : layer1 pass-B  acc1 = bias + Whh1*h1_{t-1} ======
        u64 acc1[4][NB];
        #pragma unroll
        for (int g = 0; g < 4; g++)
            #pragma unroll
            for (int b = 0; b < NB; b++) acc1[g][b] = pack2(bias1[g], 0.f);
        #pragma unroll 4
        for (int k = 0; k < HD; k += 4) {
            ulonglong2 w[4], h[NB];
            #pragma unroll
            for (int g = 0; g < 4; g++)
                w[g] = *reinterpret_cast<const ulonglong2*>(&sW1h[(u + 64 * g) * WP + k]);
            #pragma unroll
            for (int b = 0; b < NB; b++)
                h[b] = *reinterpret_cast<const ulonglong2*>(&sH1[(b0 + b) * WP + k]);
            #pragma unroll
            for (int g = 0; g < 4; g++)
                #pragma unroll
                for (int b = 0; b < NB; b++) {
                    ffma2(acc1[g][b], w[g].x, h[b].x);
                    ffma2(acc1[g][b], w[g].y, h[b].y);
                }
        }

        pairbar(barid);    // pair-mate done reading sH0 old, sH1 old, sX old
        #pragma unroll
        for (int b = 0; b < NB; b++) sH0[(b0 + b) * WP + u] = hnew0[b];
        if (lx < 32) sX[bpre * ID + ipre] = xpre;
        pairbar(barid);    // new h0_t (and x_{t+1}) visible within pair

        // ======== phase 2 : layer1 pass-A  acc1 += Wih1*h0_t =================
        #pragma unroll 4
        for (int k = 0; k < HD; k += 4) {
            ulonglong2 w[4], h[NB];
            #pragma unroll
            for (int g = 0; g < 4; g++)
                w[g] = *reinterpret_cast<const ulonglong2*>(&sW1i[(u + 64 * g) * WP + k]);
            #pragma unroll
            for (int b = 0; b < NB; b++)
                h[b] = *reinterpret_cast<const ulonglong2*>(&sH0[(b0 + b) * WP + k]);
            #pragma unroll
            for (int g = 0; g < 4; g++)
                #pragma unroll
                for (int b = 0; b < NB; b++) {
                    ffma2(acc1[g][b], w[g].x, h[b].x);
                    ffma2(acc1[g][b], w[g].y, h[b].y);
                }
        }
        float hnew1[NB];
        #pragma unroll
        for (int b = 0; b < NB; b++) {
            float gi = fsig   (red2(acc1[0][b]));
            float gf = fsig   (red2(acc1[1][b]));
            float gg = tanhapx(red2(acc1[2][b]));
            float go = fsig   (red2(acc1[3][b]));
            c1[b] = gf * c1[b] + gi * gg;
            hnew1[b] = go * tanhapx(c1[b]);
        }
        // sH1 old reads happened in phase 1c (before the two pairbars above),
        // so stores here are safe; make them visible before next step's 1c:
        #pragma unroll
        for (int b = 0; b < NB; b++) sH1[(b0 + b) * WP + u] = hnew1[b];
        pairbar(barid);
    }

    __syncthreads();       // all pairs done; final sH1 stable CTA-wide

    // ================= MLP head =================
    float* W1s = sW0;      // reuse: W1 transposed [k][n]
    for (int e = t; e < HD * HD; e += THREADS) {
        int n = e >> 6, k = e & 63;
        W1s[k * 64 + n] = W1[e];
    }
    __syncthreads();

    float bb1 = b1[u];
    float zv[NB];
    #pragma unroll
    for (int b = 0; b < NB; b++) {
        float s = bb1;
        #pragma unroll 8
        for (int k = 0; k < HD; k++)
            s += W1s[k * 64 + u] * sH1[(b0 + b) * WP + k];
        zv[b] = fmaxf(s, 0.f);
    }
    __syncthreads();
    float* sZ = sH0;       // reuse
    #pragma unroll
    for (int b = 0; b < NB; b++) sZ[(b0 + b) * WP + u] = zv[b];
    __syncthreads();

    for (int e = t; e < BTILE * 12; e += THREADS) {
        int b = e / 12, o = e % 12;
        float s = __ldg(&b2[o]);
        #pragma unroll 8
        for (int n = 0; n < HD; n++)
            s += __ldg(&W2[o * 64 + n]) * sZ[b * WP + n];
        out[(size_t)(bBase + b) * 12 + o] = s;
    }
}

extern "C" void kernel_launch(void* const* d_in, const int* in_sizes, int n_in,
                              void* d_out, int out_size)
{
    (void)in_sizes; (void)n_in; (void)out_size;
    const size_t smem = (size_t)(3 * GD * WP + 2 * BTILE * WP + BTILE * ID) * sizeof(float);
    cudaFuncSetAttribute(weather_lstm_kernel,
                         cudaFuncAttributeMaxDynamicSharedMemorySize, (int)smem);
    weather_lstm_kernel<<<NGRID, THREADS, smem>>>(
        (const float*)d_in[0],
        (const float*)d_in[1],  (const float*)d_in[2],
        (const float*)d_in[3],  (const float*)d_in[4],
        (const float*)d_in[5],  (const float*)d_in[6],
        (const float*)d_in[7],  (const float*)d_in[8],
        (const float*)d_in[9],  (const float*)d_in[10],
        (const float*)d_in[11], (const float*)d_in[12],
        (float*)d_out);
}

// round 4
// speedup vs baseline: 1.3611x; 1.1606x over previous
#include <cuda_runtime.h>

#define THREADS 256
#define BT      28      // batches per CTA
#define NB      7       // batches per thread (and per warp-pair)
#define HD      64      // hidden
#define GD      256     // 4*H
#define TT      168
#define ID      4
#define BATCH   4096
#define WP      68      // padded row stride: stride%32==4 -> conflict-free LDS.128
#define NGRID   147     // ceil(4096/28)

typedef unsigned long long u64;

__device__ __forceinline__ void ffma2(u64 &d, u64 a, u64 b) {
    asm("fma.rn.f32x2 %0, %1, %2, %0;" : "+l"(d) : "l"(a), "l"(b));
}
__device__ __forceinline__ float red2(u64 v) {
    return __uint_as_float((unsigned)v) + __uint_as_float((unsigned)(v >> 32));
}
__device__ __forceinline__ u64 pack2(float lo, float hi) {
    return (u64)__float_as_uint(lo) | ((u64)__float_as_uint(hi) << 32);
}
__device__ __forceinline__ float tanhapx(float x) {
    float y; asm("tanh.approx.f32 %0, %1;" : "=f"(y) : "f"(x)); return y;
}
__device__ __forceinline__ float fsig(float x) {       // 1 MUFU + fma
    return fmaf(0.5f, tanhapx(0.5f * x), 0.5f);
}
// 64-thread named barrier: warp-pair scoped sync (ids 1..4)
__device__ __forceinline__ void pairbar(int id) {
    asm volatile("bar.sync %0, 64;" :: "r"(id) : "memory");
}

extern "C" __global__ void __launch_bounds__(THREADS, 1)
weather_lstm_kernel(const float* __restrict__ x,
                    const float* __restrict__ Wih0, const float* __restrict__ Whh0,
                    const float* __restrict__ bih0, const float* __restrict__ bhh0,
                    const float* __restrict__ Wih1, const float* __restrict__ Whh1,
                    const float* __restrict__ bih1, const float* __restrict__ bhh1,
                    const float* __restrict__ W1,  const float* __restrict__ b1,
                    const float* __restrict__ W2,  const float* __restrict__ b2,
                    float* __restrict__ out)
{
    extern __shared__ float sm[];
    float* sW0  = sm;                       // Whh0 [256][68]
    float* sW1i = sW0  + GD * WP;           // Wih1 [256][68]
    float* sW1h = sW1i + GD * WP;           // Whh1 [256][68]
    float* sH0  = sW1h + GD * WP;           // h layer0 [28][68]   (pair-private rows)
    float* sH1  = sH0  + BT * WP;           // h layer1 [28][68]   (pair-private rows)
    float* sX   = sH1  + BT * WP;           // x_t [28][4]         (pair-private rows)

    const int t     = threadIdx.x;
    const int u     = t & 63;               // hidden unit owned by this thread
    const int pid   = t >> 6;               // warp-pair id (0..3)
    const int b0    = pid * NB;             // first batch of this pair
    const int barid = pid + 1;              // named barrier id
    const int bBase = blockIdx.x * BT;

    // ---- preload weights into SMEM ----
    for (int e = t; e < GD * HD; e += THREADS) {
        int j = e >> 6, k = e & 63;
        sW0 [j * WP + k] = Whh0[e];
        sW1i[j * WP + k] = Wih1[e];
        sW1h[j * WP + k] = Whh1[e];
    }
    for (int e = t; e < BT * WP; e += THREADS) { sH0[e] = 0.f; sH1[e] = 0.f; }
    // pair-private x load: first 28 threads of each pair load its 7 batches x 4 inputs
    const int lx   = u;                      // 0..63 within pair
    const int bpre = b0 + (lx >> 2);         // local batch for x duty
    const int ipre = lx & 3;
    const bool xok = (lx < 4 * NB) && (bBase + bpre < BATCH);
    if (xok)
        sX[bpre * ID + ipre] = x[(size_t)(bBase + bpre) * (TT * ID) + ipre];
    else if (lx < 4 * NB)
        sX[bpre * ID + ipre] = 0.f;

    // ---- per-thread constants ----
    float bias0[4], bias1[4], w0x[4][4];
    #pragma unroll
    for (int g = 0; g < 4; g++) {
        int j = u + 64 * g;
        bias0[g] = bih0[j] + bhh0[j];
        bias1[g] = bih1[j] + bhh1[j];
        #pragma unroll
        for (int i = 0; i < ID; i++) w0x[g][i] = Wih0[j * ID + i];
    }
    float c0[NB], c1[NB];
    #pragma unroll
    for (int b = 0; b < NB; b++) { c0[b] = 0.f; c1[b] = 0.f; }

    __syncthreads();     // weights + initial state visible to all

    for (int step = 0; step < TT; step++) {
        // prefetch x for step+1 (hidden behind phase-1 matvecs)
        float xpre = 0.f;
        if (xok && step + 1 < TT)
            xpre = x[(size_t)(bBase + bpre) * (TT * ID) + (step + 1) * ID + ipre];

        // ======== phase 1a : layer0  acc0 = bias + Wih0*x + Whh0*h0_{t-1} ====
        u64 acc0[4][NB];
        #pragma unroll
        for (int b = 0; b < NB; b++) {
            float4 xb = *reinterpret_cast<const float4*>(&sX[(b0 + b) * ID]);
            #pragma unroll
            for (int g = 0; g < 4; g++) {
                float a = bias0[g] + w0x[g][0] * xb.x + w0x[g][1] * xb.y
                                   + w0x[g][2] * xb.z + w0x[g][3] * xb.w;
                acc0[g][b] = pack2(a, 0.f);
            }
        }
        #pragma unroll 8
        for (int k = 0; k < HD; k += 4) {
            ulonglong2 w[4], h[NB];
            #pragma unroll
            for (int g = 0; g < 4; g++)
                w[g] = *reinterpret_cast<const ulonglong2*>(&sW0[(u + 64 * g) * WP + k]);
            #pragma unroll
            for (int b = 0; b < NB; b++)
                h[b] = *reinterpret_cast<const ulonglong2*>(&sH0[(b0 + b) * WP + k]);
            #pragma unroll
            for (int g = 0; g < 4; g++)
                #pragma unroll
                for (int b = 0; b < NB; b++) {
                    ffma2(acc0[g][b], w[g].x, h[b].x);
                    ffma2(acc0[g][b], w[g].y, h[b].y);
                }
        }

        // ======== phase 1b : layer0 activations (MUFU) — overlaps with 1c ====
        float hnew0[NB];
        #pragma unroll
        for (int b = 0; b < NB; b++) {
            float gi = fsig   (red2(acc0[0][b]));
            float gf = fsig   (red2(acc0[1][b]));
            float gg = tanhapx(red2(acc0[2][b]));
            float go = fsig   (red2(acc0[3][b]));
            c0[b] = gf * c0[b] + gi * gg;
            hnew0[b] = go * tanhapx(c0[b]);
        }

        // ======== phase 1c : layer1 pass-B  acc1 = bias + Whh1*h1_{t-1} ======
        u64 acc1[4][NB];
        #pragma unroll
        for (int g = 0; g < 4; g++)
            #pragma unroll
            for (int b = 0; b < NB; b++) acc1[g][b] = pack2(bias1[g], 0.f);
        #pragma unroll 4
        for (int k = 0; k < HD; k += 4) {
            ulonglong2 w[4], h[NB];
            #pragma unroll
            for (int g = 0; g < 4; g++)
                w[g] = *reinterpret_cast<const ulonglong2*>(&sW1h[(u + 64 * g) * WP + k]);
            #pragma unroll
            for (int b = 0; b < NB; b++)
                h[b] = *reinterpret_cast<const ulonglong2*>(&sH1[(b0 + b) * WP + k]);
            #pragma unroll
            for (int g = 0; g < 4; g++)
                #pragma unroll
                for (int b = 0; b < NB; b++) {
                    ffma2(acc1[g][b], w[g].x, h[b].x);
                    ffma2(acc1[g][b], w[g].y, h[b].y);
                }
        }

        pairbar(barid);    // pair-mate done reading sH0 old, sH1 old, sX old
        #pragma unroll
        for (int b = 0; b < NB; b++) sH0[(b0 + b) * WP + u] = hnew0[b];
        if (lx < 4 * NB) sX[bpre * ID + ipre] = xpre;
        pairbar(barid);    // new h0_t (and x_{t+1}) visible within pair

        // ======== phase 2 : layer1 pass-A  acc1 += Wih1*h0_t =================
        #pragma unroll 8
        for (int k = 0; k < HD; k += 4) {
            ulonglong2 w[4], h[NB];
            #pragma unroll
            for (int g = 0; g < 4; g++)
                w[g] = *reinterpret_cast<const ulonglong2*>(&sW1i[(u + 64 * g) * WP + k]);
            #pragma unroll
            for (int b = 0; b < NB; b++)
                h[b] = *reinterpret_cast<const ulonglong2*>(&sH0[(b0 + b) * WP + k]);
            #pragma unroll
            for (int g = 0; g < 4; g++)
                #pragma unroll
                for (int b = 0; b < NB; b++) {
                    ffma2(acc1[g][b], w[g].x, h[b].x);
                    ffma2(acc1[g][b], w[g].y, h[b].y);
                }
        }
        float hnew1[NB];
        #pragma unroll
        for (int b = 0; b < NB; b++) {
            float gi = fsig   (red2(acc1[0][b]));
            float gf = fsig   (red2(acc1[1][b]));
            float gg = tanhapx(red2(acc1[2][b]));
            float go = fsig   (red2(acc1[3][b]));
            c1[b] = gf * c1[b] + gi * gg;
            hnew1[b] = go * tanhapx(c1[b]);
        }
        // sH1 old reads happened in phase 1c (before the two pairbars above)
        #pragma unroll
        for (int b = 0; b < NB; b++) sH1[(b0 + b) * WP + u] = hnew1[b];
        pairbar(barid);    // h1_t visible before next step's 1c
    }

    __syncthreads();       // all pairs done; final sH1 stable CTA-wide

    // ================= MLP head =================
    float* W1s = sW0;      // reuse: W1 transposed [k][n]
    for (int e = t; e < HD * HD; e += THREADS) {
        int n = e >> 6, k = e & 63;
        W1s[k * 64 + n] = W1[e];
    }
    __syncthreads();

    float bb1 = b1[u];
    float zv[NB];
    #pragma unroll
    for (int b = 0; b < NB; b++) {
        float s = bb1;
        #pragma unroll 8
        for (int k = 0; k < HD; k++)
            s += W1s[k * 64 + u] * sH1[(b0 + b) * WP + k];
        zv[b] = fmaxf(s, 0.f);
    }
    __syncthreads();
    float* sZ = sH0;       // reuse
    #pragma unroll
    for (int b = 0; b < NB; b++) sZ[(b0 + b) * WP + u] = zv[b];
    __syncthreads();

    for (int e = t; e < BT * 12; e += THREADS) {
        int b = e / 12, o = e % 12;
        if (bBase + b < BATCH) {
            float s = __ldg(&b2[o]);
            #pragma unroll 8
            for (int n = 0; n < HD; n++)
                s += __ldg(&W2[o * 64 + n]) * sZ[b * WP + n];
            out[(size_t)(bBase + b) * 12 + o] = s;
        }
    }
}

extern "C" void kernel_launch(void* const* d_in, const int* in_sizes, int n_in,
                              void* d_out, int out_size)
{
    (void)in_sizes; (void)n_in; (void)out_size;
    const size_t smem = (size_t)(3 * GD * WP + 2 * BT * WP + BT * ID) * sizeof(float);
    cudaFuncSetAttribute(weather_lstm_kernel,
                         cudaFuncAttributeMaxDynamicSharedMemorySize, (int)smem);
    weather_lstm_kernel<<<NGRID, THREADS, smem>>>(
        (const float*)d_in[0],
        (const float*)d_in[1],  (const float*)d_in[2],
        (const float*)d_in[3],  (const float*)d_in[4],
        (const float*)d_in[5],  (const float*)d_in[6],
        (const float*)d_in[7],  (const float*)d_in[8],
        (const float*)d_in[9],  (const float*)d_in[10],
        (const float*)d_in[11], (const float*)d_in[12],
        (float*)d_out);
}